// round 14
// baseline (speedup 1.0000x reference)
#include <cuda_runtime.h>
#include <cuda_bf16.h>
#include <cuda_fp16.h>
#include <cstdint>
#include <math.h>

#define BATCH 16
#define SEQ   512
#define DMODEL 1024
#define NHEAD 16
#define DK    64
#define BH    (BATCH * NHEAD)
#define MTOT (BATCH * SEQ)

// ===========================================================================
// Portable PTX helpers
// ===========================================================================
__device__ __forceinline__ uint32_t smem_to_u32(const void* p) {
    uint32_t a;
    asm("{ .reg .u64 t; cvta.to.shared.u64 t, %1; cvt.u32.u64 %0, t; }" : "=r"(a) : "l"(p));
    return a;
}
__device__ __forceinline__ void cp_async16(uint32_t smem_addr, const void* gptr) {
    asm volatile("cp.async.cg.shared.global [%0], [%1], 16;" :: "r"(smem_addr), "l"(gptr) : "memory");
}
__device__ __forceinline__ void cp_commit() { asm volatile("cp.async.commit_group;" ::: "memory"); }
__device__ __forceinline__ void cp_wait1()  { asm volatile("cp.async.wait_group 1;" ::: "memory"); }
__device__ __forceinline__ void cp_wait0()  { asm volatile("cp.async.wait_group 0;" ::: "memory"); }

#define LDSM_X4(r0, r1, r2, r3, addr) \
    asm volatile("ldmatrix.sync.aligned.m8n8.x4.shared.b16 {%0,%1,%2,%3}, [%4];" \
        : "=r"(r0), "=r"(r1), "=r"(r2), "=r"(r3) : "r"(addr))

#define LDSM_X2(r0, r1, addr) \
    asm volatile("ldmatrix.sync.aligned.m8n8.x2.shared.b16 {%0,%1}, [%2];" \
        : "=r"(r0), "=r"(r1) : "r"(addr))

#define LDSM_X2_T(r0, r1, addr) \
    asm volatile("ldmatrix.sync.aligned.m8n8.x2.trans.shared.b16 {%0,%1}, [%2];" \
        : "=r"(r0), "=r"(r1) : "r"(addr))

#define MMA16816(c, a, b) \
    asm volatile("mma.sync.aligned.m16n8k16.row.col.f32.bf16.bf16.f32 " \
        "{%0,%1,%2,%3}, {%4,%5,%6,%7}, {%8,%9}, {%0,%1,%2,%3};" \
        : "+f"((c)[0]), "+f"((c)[1]), "+f"((c)[2]), "+f"((c)[3]) \
        : "r"((a)[0]), "r"((a)[1]), "r"((a)[2]), "r"((a)[3]), "r"((b)[0]), "r"((b)[1]))

// ===========================================================================
// Scratch
// ===========================================================================
__device__ __nv_bfloat16 g_Qh[(size_t)MTOT * DMODEL];
__device__ __nv_bfloat16 g_Ql[(size_t)MTOT * DMODEL];
__device__ __nv_bfloat16 g_Kh[(size_t)MTOT * DMODEL];
__device__ __nv_bfloat16 g_Kl[(size_t)MTOT * DMODEL];
__device__ __nv_bfloat16 g_Vh[(size_t)MTOT * DMODEL];
__device__ __nv_bfloat16 g_Vl[(size_t)MTOT * DMODEL];
__device__ float g_Ctx[(size_t)MTOT * DMODEL];
__device__ __half g_Pm[(size_t)BH * SEQ * SEQ];

// ===========================================================================
// HMMA GEMM core (bf16x3 from fp32 inputs), 128x128 tile, BK=32, 2-stage,
// 2 CTAs/SM. Loader: LDG fp32 -> in-register hi/lo split -> STS.
// ===========================================================================
#define GK 1024
#define NK32 (GK / 32)
#define T_STRIDE 40
#define TILE_B (128 * T_STRIDE * 2)
#define STAGE_B (4 * TILE_B)
#define GEMM_SMEM (2 * STAGE_B)   // 81920

__device__ __forceinline__ void cvt_hilo(const float4 v, uint32_t* hi2, uint32_t* lo2)
{
    __nv_bfloat16 h0 = __float2bfloat16(v.x);
    __nv_bfloat16 h1 = __float2bfloat16(v.y);
    __nv_bfloat16 h2 = __float2bfloat16(v.z);
    __nv_bfloat16 h3 = __float2bfloat16(v.w);
    __nv_bfloat162 p0(h0, h1), p1(h2, h3);
    hi2[0] = *reinterpret_cast<uint32_t*>(&p0);
    hi2[1] = *reinterpret_cast<uint32_t*>(&p1);
    __nv_bfloat162 q0(__float2bfloat16(v.x - __bfloat162float(h0)),
                      __float2bfloat16(v.y - __bfloat162float(h1)));
    __nv_bfloat162 q1(__float2bfloat16(v.z - __bfloat162float(h2)),
                      __float2bfloat16(v.w - __bfloat162float(h3)));
    lo2[0] = *reinterpret_cast<uint32_t*>(&q0);
    lo2[1] = *reinterpret_cast<uint32_t*>(&q1);
}

__device__ __forceinline__ void
gemm_core_f32(const float* __restrict__ A, const float* __restrict__ B,
              const float* __restrict__ bias, float* __restrict__ C,
              __nv_bfloat16* __restrict__ Chi, __nv_bfloat16* __restrict__ Clo,
              char* smem, int mBase, int nBase)
{
    const int tid  = threadIdx.x;
    const int lane = tid & 31;
    const int wid  = tid >> 5;
    const int wm   = wid & 3;
    const int wn   = wid >> 2;
    const uint32_t su32 = smem_to_u32(smem);

    float c[2][8][4];
#pragma unroll
    for (int mf = 0; mf < 2; mf++)
#pragma unroll
        for (int nf = 0; nf < 8; nf++)
#pragma unroll
            for (int j = 0; j < 4; j++) c[mf][nf][j] = 0.f;

    const int lr = tid >> 1;              // row 0..127
    const int lk = (tid & 1) * 16;        // elem 0/16
    const float* gpA = A + (size_t)(mBase + lr) * GK + lk;
    const float* gpB = B + (size_t)(nBase + lr) * GK + lk;
    const uint32_t soff = (uint32_t)(lr * T_STRIDE + lk) * 2;   // bytes

    float4 ra[4], rb[4];
    auto ldg_chunk = [&](int kc) {
        const float* pa = gpA + kc * 32;
        const float* pb = gpB + kc * 32;
#pragma unroll
        for (int j = 0; j < 4; j++) {
            ra[j] = *reinterpret_cast<const float4*>(pa + j * 4);
            rb[j] = *reinterpret_cast<const float4*>(pb + j * 4);
        }
    };
    auto sts_chunk = [&](int st) {
        char* base = smem + (size_t)st * STAGE_B + soff;
        uint32_t ah[8], al[8], bh[8], bl[8];
#pragma unroll
        for (int j = 0; j < 4; j++) {
            cvt_hilo(ra[j], ah + 2 * j, al + 2 * j);
            cvt_hilo(rb[j], bh + 2 * j, bl + 2 * j);
        }
        *reinterpret_cast<uint4*>(base)          = make_uint4(ah[0], ah[1], ah[2], ah[3]);
        *reinterpret_cast<uint4*>(base + 16)     = make_uint4(ah[4], ah[5], ah[6], ah[7]);
        *reinterpret_cast<uint4*>(base + TILE_B)      = make_uint4(al[0], al[1], al[2], al[3]);
        *reinterpret_cast<uint4*>(base + TILE_B + 16) = make_uint4(al[4], al[5], al[6], al[7]);
        *reinterpret_cast<uint4*>(base + 2 * TILE_B)      = make_uint4(bh[0], bh[1], bh[2], bh[3]);
        *reinterpret_cast<uint4*>(base + 2 * TILE_B + 16) = make_uint4(bh[4], bh[5], bh[6], bh[7]);
        *reinterpret_cast<uint4*>(base + 3 * TILE_B)      = make_uint4(bl[0], bl[1], bl[2], bl[3]);
        *reinterpret_cast<uint4*>(base + 3 * TILE_B + 16) = make_uint4(bl[4], bl[5], bl[6], bl[7]);
    };

    ldg_chunk(0);
    sts_chunk(0);
    ldg_chunk(1);

    const int lrow = lane & 15;
    const int lcol = (lane >> 4) * 8;

    for (int i = 0; i < NK32; i++) {
        __syncthreads();

        const uint32_t sb = su32 + (uint32_t)(i & 1) * STAGE_B;
#pragma unroll
        for (int kh = 0; kh < 32; kh += 16) {
            uint32_t bhf[8][2], blf[8][2];
#pragma unroll
            for (int g = 0; g < 4; g++) {
                uint32_t addr = sb + 2 * TILE_B +
                    (uint32_t)((wn * 64 + g * 16 + lrow) * T_STRIDE + kh + lcol) * 2;
                LDSM_X4(bhf[g * 2][0], bhf[g * 2 + 1][0],
                        bhf[g * 2][1], bhf[g * 2 + 1][1], addr);
                LDSM_X4(blf[g * 2][0], blf[g * 2 + 1][0],
                        blf[g * 2][1], blf[g * 2 + 1][1], addr + TILE_B);
            }
#pragma unroll
            for (int mf = 0; mf < 2; mf++) {
                uint32_t aaddr = sb +
                    (uint32_t)((wm * 32 + mf * 16 + lrow) * T_STRIDE + kh + lcol) * 2;
                uint32_t ah[4], al[4];
                LDSM_X4(ah[0], ah[1], ah[2], ah[3], aaddr);
                LDSM_X4(al[0], al[1], al[2], al[3], aaddr + TILE_B);
#pragma unroll
                for (int nf = 0; nf < 8; nf++) {
                    MMA16816(c[mf][nf], ah, bhf[nf]);
                    MMA16816(c[mf][nf], ah, blf[nf]);
                    MMA16816(c[mf][nf], al, bhf[nf]);
                }
            }
        }
        __syncthreads();

        if (i + 1 < NK32) {
            sts_chunk((i + 1) & 1);
            if (i + 2 < NK32) ldg_chunk(i + 2);
        }
    }

#pragma unroll
    for (int mf = 0; mf < 2; mf++) {
        const int row0 = mBase + wm * 32 + mf * 16 + (lane >> 2);
#pragma unroll
        for (int nf = 0; nf < 8; nf++) {
            const int col = nBase + wn * 64 + nf * 8 + (lane & 3) * 2;
            const float b0 = bias[col], b1 = bias[col + 1];
            float v00 = c[mf][nf][0] + b0, v01 = c[mf][nf][1] + b1;
            float v10 = c[mf][nf][2] + b0, v11 = c[mf][nf][3] + b1;
            if (Chi) {
                __nv_bfloat16 h00 = __float2bfloat16(v00), h01 = __float2bfloat16(v01);
                __nv_bfloat16 h10 = __float2bfloat16(v10), h11 = __float2bfloat16(v11);
                size_t o0 = (size_t)row0 * DMODEL + col, o1 = (size_t)(row0 + 8) * DMODEL + col;
                *reinterpret_cast<__nv_bfloat162*>(Chi + o0) = __nv_bfloat162(h00, h01);
                *reinterpret_cast<__nv_bfloat162*>(Chi + o1) = __nv_bfloat162(h10, h11);
                *reinterpret_cast<__nv_bfloat162*>(Clo + o0) = __nv_bfloat162(
                    __float2bfloat16(v00 - __bfloat162float(h00)),
                    __float2bfloat16(v01 - __bfloat162float(h01)));
                *reinterpret_cast<__nv_bfloat162*>(Clo + o1) = __nv_bfloat162(
                    __float2bfloat16(v10 - __bfloat162float(h10)),
                    __float2bfloat16(v11 - __bfloat162float(h11)));
            } else {
                *reinterpret_cast<float2*>(C + (size_t)row0 * DMODEL + col)       = make_float2(v00, v01);
                *reinterpret_cast<float2*>(C + (size_t)(row0 + 8) * DMODEL + col) = make_float2(v10, v11);
            }
        }
    }
}

__global__ void __launch_bounds__(256, 2)
gemm_qkv(const float* __restrict__ q, const float* __restrict__ k, const float* __restrict__ v,
         const float* __restrict__ wq, const float* __restrict__ wk, const float* __restrict__ wv,
         const float* __restrict__ b0, const float* __restrict__ b1, const float* __restrict__ b2,
         __nv_bfloat16* __restrict__ o0h, __nv_bfloat16* __restrict__ o0l,
         __nv_bfloat16* __restrict__ o1h, __nv_bfloat16* __restrict__ o1l,
         __nv_bfloat16* __restrict__ o2h, __nv_bfloat16* __restrict__ o2l)
{
    extern __shared__ __align__(128) char smem[];
    const int z = blockIdx.z;
    const float* A = (z == 0) ? q : ((z == 1) ? k : v);
    const float* W = (z == 0) ? wq : ((z == 1) ? wk : wv);
    const float* bias = (z == 0) ? b0 : ((z == 1) ? b1 : b2);
    __nv_bfloat16* oh = (z == 0) ? o0h : ((z == 1) ? o1h : o2h);
    __nv_bfloat16* ol = (z == 0) ? o0l : ((z == 1) ? o1l : o2l);
    gemm_core_f32(A, W, bias, nullptr, oh, ol, smem, blockIdx.y * 128, blockIdx.x * 128);
}

__global__ void __launch_bounds__(256, 2)
gemm_out(const float* __restrict__ A, const float* __restrict__ W,
         const float* __restrict__ bias, float* __restrict__ C)
{
    extern __shared__ __align__(128) char smem[];
    gemm_core_f32(A, W, bias, C, nullptr, nullptr, smem, blockIdx.y * 128, blockIdx.x * 128);
}

// ===========================================================================
// Fully fused attention: 32 s-rows per CTA, 512 threads (16 warps, 2x8 grid),
// 2 CTAs/SM. (round-13 configuration; ctx epilogue now writes fp32)
// ===========================================================================
#define S_STRIDE 516
#define FA_SROWS 32
#define FA_SBYTES (FA_SROWS * S_STRIDE * 4)
#define FS_TSTRIDE 72
#define QTILE (FA_SROWS * FS_TSTRIDE)
#define QTILEB (QTILE * 2)
#define KTILE (64 * FS_TSTRIDE)
#define KTILEB (KTILE * 2)
#define FA_SMEM (FA_SBYTES + 2 * QTILEB + 4 * KTILEB)

__global__ void __launch_bounds__(512, 2)
fused_attention(const float* __restrict__ rel_bias)
{
    extern __shared__ __align__(128) char fsmem[];
    float* S = reinterpret_cast<float*>(fsmem);
    const uint32_t sbase = smem_to_u32(fsmem);
    const uint32_t uQh  = sbase + FA_SBYTES;
    const uint32_t uQl  = uQh + QTILEB;
    const uint32_t uK0h = uQl + QTILEB;
    const uint32_t uK0l = uK0h + KTILEB;
    const uint32_t uK1h = uK0l + KTILEB;
    const uint32_t uK1l = uK1h + KTILEB;

    const int s0 = (gridDim.x - 1 - blockIdx.x) * FA_SROWS;
    const int bh = blockIdx.y;
    const int b  = bh >> 4;
    const int h  = bh & 15;
    const int tid = threadIdx.x, lane = tid & 31, wid = tid >> 5;
    const int wm = wid & 1;
    const int wn = wid >> 1;

    const int ntiles = s0 / 64 + 1;
    const int lrow = lane & 15;
    const int lcol = (lane >> 4) * 8;

    const int klr = tid >> 3;
    const int kcb = (tid & 7) * 16;
    const int qlr = tid >> 3;
    const int qcb = (tid & 7) * 16;

    // ---------------- Phase 1: scores -> S ----------------
    {
        if (tid < 256) {
            const char* gQh = (const char*)(g_Qh + ((size_t)(b * SEQ + s0 + qlr)) * DMODEL + h * DK);
            const char* gQl = (const char*)(g_Ql + ((size_t)(b * SEQ + s0 + qlr)) * DMODEL + h * DK);
            cp_async16(uQh + qlr * 144 + qcb, gQh + qcb);
            cp_async16(uQl + qlr * 144 + qcb, gQl + qcb);
        }
        const char* gKh = (const char*)(g_Kh + ((size_t)(b * SEQ + klr)) * DMODEL + h * DK);
        const char* gKl = (const char*)(g_Kl + ((size_t)(b * SEQ + klr)) * DMODEL + h * DK);
        cp_async16(uK0h + klr * 144 + kcb, gKh + kcb);
        cp_async16(uK0l + klr * 144 + kcb, gKl + kcb);
        cp_commit();
    }
    if (ntiles > 1) {
        const char* gKh = (const char*)(g_Kh + ((size_t)(b * SEQ + 64 + klr)) * DMODEL + h * DK);
        const char* gKl = (const char*)(g_Kl + ((size_t)(b * SEQ + 64 + klr)) * DMODEL + h * DK);
        cp_async16(uK1h + klr * 144 + kcb, gKh + kcb);
        cp_async16(uK1l + klr * 144 + kcb, gKl + kcb);
        cp_commit();
    }

    for (int t = 0; t < ntiles; t++) {
        const int t0 = t * 64;
        if (t + 1 < ntiles) cp_wait1(); else cp_wait0();
        __syncthreads();

        const uint32_t uKh = (t & 1) ? uK1h : uK0h;
        const uint32_t uKl = (t & 1) ? uK1l : uK0l;

        float c[4];
#pragma unroll
        for (int j = 0; j < 4; j++) c[j] = 0.f;

        const uint32_t brow_off = (uint32_t)((wn * 8 + (lane & 7)) * FS_TSTRIDE +
                                             ((lane >> 3) & 1) * 8) * 2;

#pragma unroll
        for (int k0 = 0; k0 < 64; k0 += 16) {
            uint32_t aoff = (uint32_t)((wm * 16 + lrow) * FS_TSTRIDE + k0 + lcol) * 2;
            uint32_t ah[4], al[4];
            LDSM_X4(ah[0], ah[1], ah[2], ah[3], uQh + aoff);
            LDSM_X4(al[0], al[1], al[2], al[3], uQl + aoff);
            uint32_t boff = brow_off + (uint32_t)k0 * 2;
            uint32_t bhf[2], blf[2];
            LDSM_X2(bhf[0], bhf[1], uKh + boff);
            LDSM_X2(blf[0], blf[1], uKl + boff);
            MMA16816(c, ah, bhf);
            MMA16816(c, ah, blf);
            MMA16816(c, al, bhf);
        }

        {
            const int r0 = wm * 16 + (lane >> 2);
            const int sg0 = s0 + r0, sg1 = sg0 + 8;
            const int col = wn * 8 + (lane & 3) * 2;
            const int tg = t0 + col;
            float2 rb0 = *reinterpret_cast<const float2*>(
                rel_bias + ((size_t)h * SEQ + sg0) * SEQ + tg);
            float2 rb1 = *reinterpret_cast<const float2*>(
                rel_bias + ((size_t)h * SEQ + sg1) * SEQ + tg);
            float v00 = c[0] * 0.125f + rb0.x; if (tg     > sg0) v00 = -INFINITY;
            float v01 = c[1] * 0.125f + rb0.y; if (tg + 1 > sg0) v01 = -INFINITY;
            float v10 = c[2] * 0.125f + rb1.x; if (tg     > sg1) v10 = -INFINITY;
            float v11 = c[3] * 0.125f + rb1.y; if (tg + 1 > sg1) v11 = -INFINITY;
            *reinterpret_cast<float2*>(&S[r0 * S_STRIDE + tg])       = make_float2(v00, v01);
            *reinterpret_cast<float2*>(&S[(r0 + 8) * S_STRIDE + tg]) = make_float2(v10, v11);
        }
        __syncthreads();

        if (t + 2 < ntiles) {
            const int tn = (t + 2) * 64;
            const uint32_t dKh = (t & 1) ? uK1h : uK0h;
            const uint32_t dKl = (t & 1) ? uK1l : uK0l;
            const char* gKh = (const char*)(g_Kh + ((size_t)(b * SEQ + tn + klr)) * DMODEL + h * DK);
            const char* gKl = (const char*)(g_Kl + ((size_t)(b * SEQ + tn + klr)) * DMODEL + h * DK);
            cp_async16(dKh + klr * 144 + kcb, gKh + kcb);
            cp_async16(dKl + klr * 144 + kcb, gKl + kcb);
            cp_commit();
        }
    }

    // ---------------- Phase 2: softmax ----------------
    const int Lt = ntiles * 64;
    for (int r = wid * 2; r < wid * 2 + 2; r++) {
        const int s = s0 + r;
        const int L = s + 1;
        float* row = S + r * S_STRIDE;

        float m = -INFINITY;
        for (int ci = lane; ci < L; ci += 32) m = fmaxf(m, row[ci]);
#pragma unroll
        for (int o = 16; o; o >>= 1) m = fmaxf(m, __shfl_xor_sync(0xffffffffu, m, o));

        float sum = 0.f;
        for (int ci = lane; ci < L; ci += 32) {
            float e = __expf(row[ci] - m);
            row[ci] = e;
            sum += e;
        }
#pragma unroll
        for (int o = 16; o; o >>= 1) sum += __shfl_xor_sync(0xffffffffu, sum, o);
        const float inv = 1.f / sum;

        __half* om = g_Pm + ((size_t)bh * SEQ + s) * SEQ;
        for (int ci = lane; ci < Lt; ci += 32) {
            float p = (ci < L) ? row[ci] * inv : 0.f;
            row[ci] = p;
            om[ci] = __float2half_rn(p);
        }
    }
    __syncthreads();

    // ---------------- Phase 3: ctx = P @ V ----------------
    float c2[4];
#pragma unroll
    for (int j = 0; j < 4; j++) c2[j] = 0.f;

    {
        const char* gVh = (const char*)(g_Vh + ((size_t)(b * SEQ + klr)) * DMODEL + h * DK);
        const char* gVl = (const char*)(g_Vl + ((size_t)(b * SEQ + klr)) * DMODEL + h * DK);
        cp_async16(uK0h + klr * 144 + kcb, gVh + kcb);
        cp_async16(uK0l + klr * 144 + kcb, gVl + kcb);
        cp_commit();
    }
    if (ntiles > 1) {
        const char* gVh = (const char*)(g_Vh + ((size_t)(b * SEQ + 64 + klr)) * DMODEL + h * DK);
        const char* gVl = (const char*)(g_Vl + ((size_t)(b * SEQ + 64 + klr)) * DMODEL + h * DK);
        cp_async16(uK1h + klr * 144 + kcb, gVh + kcb);
        cp_async16(uK1l + klr * 144 + kcb, gVl + kcb);
        cp_commit();
    }

    __nv_bfloat16* tPh = reinterpret_cast<__nv_bfloat16*>(fsmem + FA_SBYTES);
    __nv_bfloat16* tPl = tPh + QTILE;

    for (int t = 0; t < ntiles; t++) {
        const int t0 = t * 64;
        if (t + 1 < ntiles) cp_wait1(); else cp_wait0();

        {
            const int pr = tid >> 4;
            const int pc = (tid & 15) * 4;
            const float* srow = S + pr * S_STRIDE + t0 + pc;
            float4 v = *reinterpret_cast<const float4*>(srow);
            __nv_bfloat16 h0 = __float2bfloat16(v.x);
            __nv_bfloat16 h1 = __float2bfloat16(v.y);
            __nv_bfloat16 h2 = __float2bfloat16(v.z);
            __nv_bfloat16 h3 = __float2bfloat16(v.w);
            __nv_bfloat16* ph = tPh + pr * FS_TSTRIDE + pc;
            __nv_bfloat16* pl = tPl + pr * FS_TSTRIDE + pc;
            *reinterpret_cast<__nv_bfloat162*>(ph)     = __nv_bfloat162(h0, h1);
            *reinterpret_cast<__nv_bfloat162*>(ph + 2) = __nv_bfloat162(h2, h3);
            *reinterpret_cast<__nv_bfloat162*>(pl)     = __nv_bfloat162(
                __float2bfloat16(v.x - __bfloat162float(h0)),
                __float2bfloat16(v.y - __bfloat162float(h1)));
            *reinterpret_cast<__nv_bfloat162*>(pl + 2) = __nv_bfloat162(
                __float2bfloat16(v.z - __bfloat162float(h2)),
                __float2bfloat16(v.w - __bfloat162float(h3)));
        }
        __syncthreads();

        const uint32_t uVh = (t & 1) ? uK1h : uK0h;
        const uint32_t uVl = (t & 1) ? uK1l : uK0l;

#pragma unroll
        for (int k0 = 0; k0 < 64; k0 += 16) {
            uint32_t aoff = (uint32_t)((wm * 16 + lrow) * FS_TSTRIDE + k0 + lcol) * 2;
            uint32_t ah[4], al[4];
            LDSM_X4(ah[0], ah[1], ah[2], ah[3], uQh + aoff);
            LDSM_X4(al[0], al[1], al[2], al[3], uQl + aoff);
            uint32_t boff = (uint32_t)((k0 + (lane & 15)) * FS_TSTRIDE + wn * 8) * 2;
            uint32_t bhf[2], blf[2];
            LDSM_X2_T(bhf[0], bhf[1], uVh + boff);
            LDSM_X2_T(blf[0], blf[1], uVl + boff);
            MMA16816(c2, ah, bhf);
            MMA16816(c2, ah, blf);
            MMA16816(c2, al, bhf);
        }
        __syncthreads();

        if (t + 2 < ntiles) {
            const int tn = (t + 2) * 64;
            const uint32_t dVh = (t & 1) ? uK1h : uK0h;
            const uint32_t dVl = (t & 1) ? uK1l : uK0l;
            const char* gVh = (const char*)(g_Vh + ((size_t)(b * SEQ + tn + klr)) * DMODEL + h * DK);
            const char* gVl = (const char*)(g_Vl + ((size_t)(b * SEQ + tn + klr)) * DMODEL + h * DK);
            cp_async16(dVh + klr * 144 + kcb, gVh + kcb);
            cp_async16(dVl + klr * 144 + kcb, gVl + kcb);
            cp_commit();
        }
    }

    // ctx epilogue (fp32)
    {
        const int r0 = wm * 16 + (lane >> 2);
        const int col = wn * 8 + (lane & 3) * 2;
#pragma unroll
        for (int half = 0; half < 2; half++) {
            const int s = s0 + r0 + half * 8;
            size_t o = ((size_t)(b * SEQ + s)) * DMODEL + h * DK + col;
            *reinterpret_cast<float2*>(g_Ctx + o) = make_float2(c2[half * 2], c2[half * 2 + 1]);
        }
    }
}

// ===========================================================================
// attn head-mean (fp16 P; half2 vectorized)
// ===========================================================================
__global__ void __launch_bounds__(256)
mean_kernel(float* __restrict__ out2)
{
    const size_t pidx = (size_t)blockIdx.x * 256 + threadIdx.x;
    const int b = (int)(pidx >> 17);
    const int r = (int)(pidx & 131071);
    const int s  = r >> 8;
    const int t2 = (r & 255) * 2;
    float2* o = reinterpret_cast<float2*>(out2) + pidx;
    if (t2 > s) { *o = make_float2(0.f, 0.f); return; }
    float s0 = 0.f, s1 = 0.f;
#pragma unroll
    for (int h = 0; h < NHEAD; h++) {
        const __half2 p = *reinterpret_cast<const __half2*>(
            g_Pm + ((size_t)(b * NHEAD + h) * SEQ + s) * SEQ + t2);
        float2 f = __half22float2(p);
        s0 += f.x; s1 += f.y;
    }
    *o = make_float2(s0 * (1.f / NHEAD), (t2 + 1 <= s) ? s1 * (1.f / NHEAD) : 0.f);
}

// ===========================================================================
// Launch
// ===========================================================================
extern "C" void kernel_launch(void* const* d_in, const int* in_sizes, int n_in,
                              void* d_out, int out_size)
{
    const float* query = (const float*)d_in[0];
    const float* key   = (const float*)d_in[1];
    const float* value = (const float*)d_in[2];
    const float* wq_w  = (const float*)d_in[3];
    const float* wq_b  = (const float*)d_in[4];
    const float* wk_w  = (const float*)d_in[5];
    const float* wk_b  = (const float*)d_in[6];
    const float* wv_w  = (const float*)d_in[7];
    const float* wv_b  = (const float*)d_in[8];
    const float* wo_w  = (const float*)d_in[9];
    const float* wo_b  = (const float*)d_in[10];
    const float* rel_bias = (const float*)d_in[11];

    float* out  = (float*)d_out;
    const size_t out1_elems = (size_t)MTOT * DMODEL;
    const size_t out2_elems = (size_t)BATCH * SEQ * SEQ;
    float* out2 = out + out1_elems;

    __nv_bfloat16 *qh, *ql, *kh, *kl, *vh, *vl;
    float* ctxP;
    cudaGetSymbolAddress((void**)&qh, g_Qh);
    cudaGetSymbolAddress((void**)&ql, g_Ql);
    cudaGetSymbolAddress((void**)&kh, g_Kh);
    cudaGetSymbolAddress((void**)&kl, g_Kl);
    cudaGetSymbolAddress((void**)&vh, g_Vh);
    cudaGetSymbolAddress((void**)&vl, g_Vl);
    cudaGetSymbolAddress((void**)&ctxP, g_Ctx);

    cudaFuncSetAttribute(fused_attention,
                         cudaFuncAttributeMaxDynamicSharedMemorySize, FA_SMEM);
    cudaFuncSetAttribute(gemm_qkv,
                         cudaFuncAttributeMaxDynamicSharedMemorySize, GEMM_SMEM);
    cudaFuncSetAttribute(gemm_out,
                         cudaFuncAttributeMaxDynamicSharedMemorySize, GEMM_SMEM);

    gemm_qkv<<<dim3(DMODEL / 128, MTOT / 128, 3), 256, GEMM_SMEM>>>(
        query, key, value, wq_w, wk_w, wv_w, wq_b, wk_b, wv_b,
        qh, ql, kh, kl, vh, vl);

    fused_attention<<<dim3(SEQ / FA_SROWS, BH), 512, FA_SMEM>>>(rel_bias);

    if ((size_t)out_size >= out1_elems + out2_elems) {
        mean_kernel<<<(unsigned)(out2_elems / 512), 256>>>(out2);
    }

    gemm_out<<<dim3(DMODEL / 128, MTOT / 128), 256, GEMM_SMEM>>>(
        ctxP, wo_w, wo_b, out);
}

// round 15
// speedup vs baseline: 1.0830x; 1.0830x over previous
#include <cuda_runtime.h>
#include <cuda_bf16.h>
#include <cuda_fp16.h>
#include <cstdint>
#include <math.h>

#define BATCH 16
#define SEQ   512
#define DMODEL 1024
#define NHEAD 16
#define DK    64
#define BH    (BATCH * NHEAD)
#define MTOT (BATCH * SEQ)

// ===========================================================================
// Portable PTX helpers
// ===========================================================================
__device__ __forceinline__ uint32_t smem_to_u32(const void* p) {
    uint32_t a;
    asm("{ .reg .u64 t; cvta.to.shared.u64 t, %1; cvt.u32.u64 %0, t; }" : "=r"(a) : "l"(p));
    return a;
}
__device__ __forceinline__ void cp_async16(uint32_t smem_addr, const void* gptr) {
    asm volatile("cp.async.cg.shared.global [%0], [%1], 16;" :: "r"(smem_addr), "l"(gptr) : "memory");
}
__device__ __forceinline__ void cp_commit() { asm volatile("cp.async.commit_group;" ::: "memory"); }
__device__ __forceinline__ void cp_wait1()  { asm volatile("cp.async.wait_group 1;" ::: "memory"); }
__device__ __forceinline__ void cp_wait0()  { asm volatile("cp.async.wait_group 0;" ::: "memory"); }

#define LDSM_X4(r0, r1, r2, r3, addr) \
    asm volatile("ldmatrix.sync.aligned.m8n8.x4.shared.b16 {%0,%1,%2,%3}, [%4];" \
        : "=r"(r0), "=r"(r1), "=r"(r2), "=r"(r3) : "r"(addr))

#define LDSM_X2(r0, r1, addr) \
    asm volatile("ldmatrix.sync.aligned.m8n8.x2.shared.b16 {%0,%1}, [%2];" \
        : "=r"(r0), "=r"(r1) : "r"(addr))

#define LDSM_X2_T(r0, r1, addr) \
    asm volatile("ldmatrix.sync.aligned.m8n8.x2.trans.shared.b16 {%0,%1}, [%2];" \
        : "=r"(r0), "=r"(r1) : "r"(addr))

#define MMA16816(c, a, b) \
    asm volatile("mma.sync.aligned.m16n8k16.row.col.f32.bf16.bf16.f32 " \
        "{%0,%1,%2,%3}, {%4,%5,%6,%7}, {%8,%9}, {%0,%1,%2,%3};" \
        : "+f"((c)[0]), "+f"((c)[1]), "+f"((c)[2]), "+f"((c)[3]) \
        : "r"((a)[0]), "r"((a)[1]), "r"((a)[2]), "r"((a)[3]), "r"((b)[0]), "r"((b)[1]))

// ===========================================================================
// Scratch
// ===========================================================================
__device__ __nv_bfloat16 g_Ahi[(size_t)3 * MTOT * DMODEL];
__device__ __nv_bfloat16 g_Alo[(size_t)3 * MTOT * DMODEL];
__device__ __nv_bfloat16 g_Whi[(size_t)4 * DMODEL * DMODEL];
__device__ __nv_bfloat16 g_Wlo[(size_t)4 * DMODEL * DMODEL];
__device__ __nv_bfloat16 g_Qh[(size_t)MTOT * DMODEL];
__device__ __nv_bfloat16 g_Ql[(size_t)MTOT * DMODEL];
__device__ __nv_bfloat16 g_Kh[(size_t)MTOT * DMODEL];
__device__ __nv_bfloat16 g_Kl[(size_t)MTOT * DMODEL];
__device__ __nv_bfloat16 g_Vh[(size_t)MTOT * DMODEL];
__device__ __nv_bfloat16 g_Vl[(size_t)MTOT * DMODEL];
__device__ __nv_bfloat16 g_Ch[(size_t)MTOT * DMODEL];
__device__ __nv_bfloat16 g_Cl[(size_t)MTOT * DMODEL];
__device__ __half g_Pm[(size_t)BH * SEQ * SEQ];

// ===========================================================================
// fp32 -> bf16 hi/lo splits
// ===========================================================================
__device__ __forceinline__ void split_store(const float4 v, __nv_bfloat16* hi,
                                            __nv_bfloat16* lo, size_t i4)
{
    __nv_bfloat16 h0 = __float2bfloat16(v.x);
    __nv_bfloat16 h1 = __float2bfloat16(v.y);
    __nv_bfloat16 h2 = __float2bfloat16(v.z);
    __nv_bfloat16 h3 = __float2bfloat16(v.w);
    __nv_bfloat162* hp = reinterpret_cast<__nv_bfloat162*>(hi);
    __nv_bfloat162* lp = reinterpret_cast<__nv_bfloat162*>(lo);
    hp[2 * i4]     = __nv_bfloat162(h0, h1);
    hp[2 * i4 + 1] = __nv_bfloat162(h2, h3);
    lp[2 * i4]     = __nv_bfloat162(__float2bfloat16(v.x - __bfloat162float(h0)),
                                    __float2bfloat16(v.y - __bfloat162float(h1)));
    lp[2 * i4 + 1] = __nv_bfloat162(__float2bfloat16(v.z - __bfloat162float(h2)),
                                    __float2bfloat16(v.w - __bfloat162float(h3)));
}

__global__ void __launch_bounds__(256)
split3_bf16(const float* __restrict__ q, const float* __restrict__ k,
            const float* __restrict__ v, __nv_bfloat16* __restrict__ hi,
            __nv_bfloat16* __restrict__ lo, int n4)
{
    int i = blockIdx.x * 256 + threadIdx.x;
    if (i >= n4) return;
    const int z = blockIdx.y;
    const float* src = (z == 0) ? q : ((z == 1) ? k : v);
    split_store(reinterpret_cast<const float4*>(src)[i], hi, lo, (size_t)z * n4 + i);
}

__global__ void __launch_bounds__(256)
split4_bf16(const float* __restrict__ w0, const float* __restrict__ w1,
            const float* __restrict__ w2, const float* __restrict__ w3,
            __nv_bfloat16* __restrict__ hi, __nv_bfloat16* __restrict__ lo, int n4)
{
    int i = blockIdx.x * 256 + threadIdx.x;
    if (i >= n4) return;
    const int z = blockIdx.y;
    const float* src = (z == 0) ? w0 : ((z == 1) ? w1 : ((z == 2) ? w2 : w3));
    split_store(reinterpret_cast<const float4*>(src)[i], hi, lo, (size_t)z * n4 + i);
}

// ===========================================================================
// HMMA GEMM core (bf16x3), 128x128 tile, BK=32, 2-stage, 2 CTAs/SM.
// ===========================================================================
#define GK 1024
#define NK32 (GK / 32)
#define T_STRIDE 40
#define TILE_B (128 * T_STRIDE * 2)
#define STAGE_B (4 * TILE_B)
#define GEMM_SMEM (2 * STAGE_B)

__device__ __forceinline__ void
gemm_core(const __nv_bfloat16* __restrict__ Ahi, const __nv_bfloat16* __restrict__ Alo,
          const __nv_bfloat16* __restrict__ Bhi, const __nv_bfloat16* __restrict__ Blo,
          const float* __restrict__ bias, float* __restrict__ C,
          __nv_bfloat16* __restrict__ Chi, __nv_bfloat16* __restrict__ Clo,
          char* smem, int mBase, int nBase)
{
    const int tid  = threadIdx.x;
    const int lane = tid & 31;
    const int wid  = tid >> 5;
    const int wm   = wid & 3;
    const int wn   = wid >> 2;
    const uint32_t su32 = smem_to_u32(smem);

    float c[2][8][4];
#pragma unroll
    for (int mf = 0; mf < 2; mf++)
#pragma unroll
        for (int nf = 0; nf < 8; nf++)
#pragma unroll
            for (int j = 0; j < 4; j++) c[mf][nf][j] = 0.f;

    const int lr = tid >> 1;
    const int lk = (tid & 1) * 16;
    const __nv_bfloat16* gp0 = Ahi + (size_t)(mBase + lr) * GK + lk;
    const __nv_bfloat16* gp1 = Alo + (size_t)(mBase + lr) * GK + lk;
    const __nv_bfloat16* gp2 = Bhi + (size_t)(nBase + lr) * GK + lk;
    const __nv_bfloat16* gp3 = Blo + (size_t)(nBase + lr) * GK + lk;
    const uint32_t soff = (uint32_t)(lr * T_STRIDE + lk) * 2;

    auto load_chunk = [&](int st, int kc) {
        uint32_t base = su32 + (uint32_t)st * STAGE_B + soff;
        const int ko = kc * 32;
        cp_async16(base,               gp0 + ko);
        cp_async16(base + 16,          gp0 + ko + 8);
        cp_async16(base + TILE_B,      gp1 + ko);
        cp_async16(base + TILE_B + 16, gp1 + ko + 8);
        cp_async16(base + 2 * TILE_B,      gp2 + ko);
        cp_async16(base + 2 * TILE_B + 16, gp2 + ko + 8);
        cp_async16(base + 3 * TILE_B,      gp3 + ko);
        cp_async16(base + 3 * TILE_B + 16, gp3 + ko + 8);
    };

    load_chunk(0, 0); cp_commit();
    load_chunk(1, 1); cp_commit();

    const int lrow = lane & 15;
    const int lcol = (lane >> 4) * 8;

    for (int i = 0; i < NK32; i++) {
        if (i + 1 < NK32) cp_wait1(); else cp_wait0();
        __syncthreads();

        const uint32_t sb = su32 + (uint32_t)(i & 1) * STAGE_B;
#pragma unroll
        for (int kh = 0; kh < 32; kh += 16) {
            uint32_t bh[8][2], bl[8][2];
#pragma unroll
            for (int g = 0; g < 4; g++) {
                uint32_t addr = sb + 2 * TILE_B +
                    (uint32_t)((wn * 64 + g * 16 + lrow) * T_STRIDE + kh + lcol) * 2;
                LDSM_X4(bh[g * 2][0], bh[g * 2 + 1][0],
                        bh[g * 2][1], bh[g * 2 + 1][1], addr);
                LDSM_X4(bl[g * 2][0], bl[g * 2 + 1][0],
                        bl[g * 2][1], bl[g * 2 + 1][1], addr + TILE_B);
            }
#pragma unroll
            for (int mf = 0; mf < 2; mf++) {
                uint32_t aaddr = sb +
                    (uint32_t)((wm * 32 + mf * 16 + lrow) * T_STRIDE + kh + lcol) * 2;
                uint32_t ah[4], al[4];
                LDSM_X4(ah[0], ah[1], ah[2], ah[3], aaddr);
                LDSM_X4(al[0], al[1], al[2], al[3], aaddr + TILE_B);
#pragma unroll
                for (int nf = 0; nf < 8; nf++) {
                    MMA16816(c[mf][nf], ah, bh[nf]);
                    MMA16816(c[mf][nf], ah, bl[nf]);
                    MMA16816(c[mf][nf], al, bh[nf]);
                }
            }
        }
        __syncthreads();

        if (i + 2 < NK32) {
            load_chunk(i & 1, i + 2);
            cp_commit();
        }
    }

#pragma unroll
    for (int mf = 0; mf < 2; mf++) {
        const int row0 = mBase + wm * 32 + mf * 16 + (lane >> 2);
#pragma unroll
        for (int nf = 0; nf < 8; nf++) {
            const int col = nBase + wn * 64 + nf * 8 + (lane & 3) * 2;
            const float b0 = bias[col], b1 = bias[col + 1];
            float v00 = c[mf][nf][0] + b0, v01 = c[mf][nf][1] + b1;
            float v10 = c[mf][nf][2] + b0, v11 = c[mf][nf][3] + b1;
            if (Chi) {
                __nv_bfloat16 h00 = __float2bfloat16(v00), h01 = __float2bfloat16(v01);
                __nv_bfloat16 h10 = __float2bfloat16(v10), h11 = __float2bfloat16(v11);
                size_t o0 = (size_t)row0 * DMODEL + col, o1 = (size_t)(row0 + 8) * DMODEL + col;
                *reinterpret_cast<__nv_bfloat162*>(Chi + o0) = __nv_bfloat162(h00, h01);
                *reinterpret_cast<__nv_bfloat162*>(Chi + o1) = __nv_bfloat162(h10, h11);
                *reinterpret_cast<__nv_bfloat162*>(Clo + o0) = __nv_bfloat162(
                    __float2bfloat16(v00 - __bfloat162float(h00)),
                    __float2bfloat16(v01 - __bfloat162float(h01)));
                *reinterpret_cast<__nv_bfloat162*>(Clo + o1) = __nv_bfloat162(
                    __float2bfloat16(v10 - __bfloat162float(h10)),
                    __float2bfloat16(v11 - __bfloat162float(h11)));
            } else {
                *reinterpret_cast<float2*>(C + (size_t)row0 * DMODEL + col)       = make_float2(v00, v01);
                *reinterpret_cast<float2*>(C + (size_t)(row0 + 8) * DMODEL + col) = make_float2(v10, v11);
            }
        }
    }
}

__global__ void __launch_bounds__(256, 2)
gemm_qkv(const __nv_bfloat16* __restrict__ Ahi, const __nv_bfloat16* __restrict__ Alo,
         const __nv_bfloat16* __restrict__ Whi, const __nv_bfloat16* __restrict__ Wlo,
         const float* __restrict__ b0, const float* __restrict__ b1, const float* __restrict__ b2,
         __nv_bfloat16* __restrict__ o0h, __nv_bfloat16* __restrict__ o0l,
         __nv_bfloat16* __restrict__ o1h, __nv_bfloat16* __restrict__ o1l,
         __nv_bfloat16* __restrict__ o2h, __nv_bfloat16* __restrict__ o2l)
{
    extern __shared__ __align__(128) char smem[];
    const int z = blockIdx.z;
    const size_t aoff = (size_t)z * MTOT * GK;
    const size_t woff = (size_t)z * DMODEL * GK;
    const float* bias = (z == 0) ? b0 : ((z == 1) ? b1 : b2);
    __nv_bfloat16* oh = (z == 0) ? o0h : ((z == 1) ? o1h : o2h);
    __nv_bfloat16* ol = (z == 0) ? o0l : ((z == 1) ? o1l : o2l);
    gemm_core(Ahi + aoff, Alo + aoff, Whi + woff, Wlo + woff,
              bias, nullptr, oh, ol, smem, blockIdx.y * 128, blockIdx.x * 128);
}

__global__ void __launch_bounds__(256, 2)
gemm_out(const __nv_bfloat16* __restrict__ Ahi, const __nv_bfloat16* __restrict__ Alo,
         const __nv_bfloat16* __restrict__ Whi, const __nv_bfloat16* __restrict__ Wlo,
         const float* __restrict__ bias, float* __restrict__ C)
{
    extern __shared__ __align__(128) char smem[];
    gemm_core(Ahi, Alo, Whi, Wlo, bias, C, nullptr, nullptr,
              smem, blockIdx.y * 128, blockIdx.x * 128);
}

// ===========================================================================
// Fully fused attention: 32 s-rows per CTA, 512 threads (16 warps, 2x8 grid),
// 2 CTAs/SM. Double-buffered K/V tiles.
// ===========================================================================
#define S_STRIDE 516
#define FA_SROWS 32
#define FA_SBYTES (FA_SROWS * S_STRIDE * 4)
#define FS_TSTRIDE 72
#define QTILE (FA_SROWS * FS_TSTRIDE)
#define QTILEB (QTILE * 2)
#define KTILE (64 * FS_TSTRIDE)
#define KTILEB (KTILE * 2)
#define FA_SMEM (FA_SBYTES + 2 * QTILEB + 4 * KTILEB)

__global__ void __launch_bounds__(512, 2)
fused_attention(const float* __restrict__ rel_bias)
{
    extern __shared__ __align__(128) char fsmem[];
    float* S = reinterpret_cast<float*>(fsmem);
    const uint32_t sbase = smem_to_u32(fsmem);
    const uint32_t uQh  = sbase + FA_SBYTES;
    const uint32_t uQl  = uQh + QTILEB;
    const uint32_t uK0h = uQl + QTILEB;
    const uint32_t uK0l = uK0h + KTILEB;
    const uint32_t uK1h = uK0l + KTILEB;
    const uint32_t uK1l = uK1h + KTILEB;

    const int s0 = (gridDim.x - 1 - blockIdx.x) * FA_SROWS;
    const int bh = blockIdx.y;
    const int b  = bh >> 4;
    const int h  = bh & 15;
    const int tid = threadIdx.x, lane = tid & 31, wid = tid >> 5;
    const int wm = wid & 1;
    const int wn = wid >> 1;

    const int ntiles = s0 / 64 + 1;
    const int lrow = lane & 15;
    const int lcol = (lane >> 4) * 8;

    const int klr = tid >> 3;
    const int kcb = (tid & 7) * 16;
    const int qlr = tid >> 3;
    const int qcb = (tid & 7) * 16;

    // ---------------- Phase 1: scores -> S ----------------
    {
        if (tid < 256) {
            const char* gQh = (const char*)(g_Qh + ((size_t)(b * SEQ + s0 + qlr)) * DMODEL + h * DK);
            const char* gQl = (const char*)(g_Ql + ((size_t)(b * SEQ + s0 + qlr)) * DMODEL + h * DK);
            cp_async16(uQh + qlr * 144 + qcb, gQh + qcb);
            cp_async16(uQl + qlr * 144 + qcb, gQl + qcb);
        }
        const char* gKh = (const char*)(g_Kh + ((size_t)(b * SEQ + klr)) * DMODEL + h * DK);
        const char* gKl = (const char*)(g_Kl + ((size_t)(b * SEQ + klr)) * DMODEL + h * DK);
        cp_async16(uK0h + klr * 144 + kcb, gKh + kcb);
        cp_async16(uK0l + klr * 144 + kcb, gKl + kcb);
        cp_commit();
    }
    if (ntiles > 1) {
        const char* gKh = (const char*)(g_Kh + ((size_t)(b * SEQ + 64 + klr)) * DMODEL + h * DK);
        const char* gKl = (const char*)(g_Kl + ((size_t)(b * SEQ + 64 + klr)) * DMODEL + h * DK);
        cp_async16(uK1h + klr * 144 + kcb, gKh + kcb);
        cp_async16(uK1l + klr * 144 + kcb, gKl + kcb);
        cp_commit();
    }

    for (int t = 0; t < ntiles; t++) {
        const int t0 = t * 64;
        if (t + 1 < ntiles) cp_wait1(); else cp_wait0();
        __syncthreads();

        const uint32_t uKh = (t & 1) ? uK1h : uK0h;
        const uint32_t uKl = (t & 1) ? uK1l : uK0l;

        float c[4];
#pragma unroll
        for (int j = 0; j < 4; j++) c[j] = 0.f;

        const uint32_t brow_off = (uint32_t)((wn * 8 + (lane & 7)) * FS_TSTRIDE +
                                             ((lane >> 3) & 1) * 8) * 2;

#pragma unroll
        for (int k0 = 0; k0 < 64; k0 += 16) {
            uint32_t aoff = (uint32_t)((wm * 16 + lrow) * FS_TSTRIDE + k0 + lcol) * 2;
            uint32_t ah[4], al[4];
            LDSM_X4(ah[0], ah[1], ah[2], ah[3], uQh + aoff);
            LDSM_X4(al[0], al[1], al[2], al[3], uQl + aoff);
            uint32_t boff = brow_off + (uint32_t)k0 * 2;
            uint32_t bhf[2], blf[2];
            LDSM_X2(bhf[0], bhf[1], uKh + boff);
            LDSM_X2(blf[0], blf[1], uKl + boff);
            MMA16816(c, ah, bhf);
            MMA16816(c, ah, blf);
            MMA16816(c, al, bhf);
        }

        {
            const int r0 = wm * 16 + (lane >> 2);
            const int sg0 = s0 + r0, sg1 = sg0 + 8;
            const int col = wn * 8 + (lane & 3) * 2;
            const int tg = t0 + col;
            float2 rb0 = *reinterpret_cast<const float2*>(
                rel_bias + ((size_t)h * SEQ + sg0) * SEQ + tg);
            float2 rb1 = *reinterpret_cast<const float2*>(
                rel_bias + ((size_t)h * SEQ + sg1) * SEQ + tg);
            float v00 = c[0] * 0.125f + rb0.x; if (tg     > sg0) v00 = -INFINITY;
            float v01 = c[1] * 0.125f + rb0.y; if (tg + 1 > sg0) v01 = -INFINITY;
            float v10 = c[2] * 0.125f + rb1.x; if (tg     > sg1) v10 = -INFINITY;
            float v11 = c[3] * 0.125f + rb1.y; if (tg + 1 > sg1) v11 = -INFINITY;
            *reinterpret_cast<float2*>(&S[r0 * S_STRIDE + tg])       = make_float2(v00, v01);
            *reinterpret_cast<float2*>(&S[(r0 + 8) * S_STRIDE + tg]) = make_float2(v10, v11);
        }
        __syncthreads();

        if (t + 2 < ntiles) {
            const int tn = (t + 2) * 64;
            const uint32_t dKh = (t & 1) ? uK1h : uK0h;
            const uint32_t dKl = (t & 1) ? uK1l : uK0l;
            const char* gKh = (const char*)(g_Kh + ((size_t)(b * SEQ + tn + klr)) * DMODEL + h * DK);
            const char* gKl = (const char*)(g_Kl + ((size_t)(b * SEQ + tn + klr)) * DMODEL + h * DK);
            cp_async16(dKh + klr * 144 + kcb, gKh + kcb);
            cp_async16(dKl + klr * 144 + kcb, gKl + kcb);
            cp_commit();
        }
    }

    // ---------------- Phase 2: softmax (2 rows per warp) ----------------
    const int Lt = ntiles * 64;
    for (int r = wid * 2; r < wid * 2 + 2; r++) {
        const int s = s0 + r;
        const int L = s + 1;
        float* row = S + r * S_STRIDE;

        float m = -INFINITY;
        for (int ci = lane; ci < L; ci += 32) m = fmaxf(m, row[ci]);
#pragma unroll
        for (int o = 16; o; o >>= 1) m = fmaxf(m, __shfl_xor_sync(0xffffffffu, m, o));

        float sum = 0.f;
        for (int ci = lane; ci < L; ci += 32) {
            float e = __expf(row[ci] - m);
            row[ci] = e;
            sum += e;
        }
#pragma unroll
        for (int o = 16; o; o >>= 1) sum += __shfl_xor_sync(0xffffffffu, sum, o);
        const float inv = 1.f / sum;

        __half* om = g_Pm + ((size_t)bh * SEQ + s) * SEQ;
        for (int ci = lane; ci < Lt; ci += 32) {
            float p = (ci < L) ? row[ci] * inv : 0.f;
            row[ci] = p;
            om[ci] = __float2half_rn(p);
        }
    }
    __syncthreads();

    // ---------------- Phase 3: ctx = P @ V ----------------
    float c2[4];
#pragma unroll
    for (int j = 0; j < 4; j++) c2[j] = 0.f;

    {
        const char* gVh = (const char*)(g_Vh + ((size_t)(b * SEQ + klr)) * DMODEL + h * DK);
        const char* gVl = (const char*)(g_Vl + ((size_t)(b * SEQ + klr)) * DMODEL + h * DK);
        cp_async16(uK0h + klr * 144 + kcb, gVh + kcb);
        cp_async16(uK0l + klr * 144 + kcb, gVl + kcb);
        cp_commit();
    }
    if (ntiles > 1) {
        const char* gVh = (const char*)(g_Vh + ((size_t)(b * SEQ + 64 + klr)) * DMODEL + h * DK);
        const char* gVl = (const char*)(g_Vl + ((size_t)(b * SEQ + 64 + klr)) * DMODEL + h * DK);
        cp_async16(uK1h + klr * 144 + kcb, gVh + kcb);
        cp_async16(uK1l + klr * 144 + kcb, gVl + kcb);
        cp_commit();
    }

    __nv_bfloat16* tPh = reinterpret_cast<__nv_bfloat16*>(fsmem + FA_SBYTES);
    __nv_bfloat16* tPl = tPh + QTILE;

    for (int t = 0; t < ntiles; t++) {
        const int t0 = t * 64;
        if (t + 1 < ntiles) cp_wait1(); else cp_wait0();

        {
            const int pr = tid >> 4;
            const int pc = (tid & 15) * 4;
            const float* srow = S + pr * S_STRIDE + t0 + pc;
            float4 v = *reinterpret_cast<const float4*>(srow);
            __nv_bfloat16 h0 = __float2bfloat16(v.x);
            __nv_bfloat16 h1 = __float2bfloat16(v.y);
            __nv_bfloat16 h2 = __float2bfloat16(v.z);
            __nv_bfloat16 h3 = __float2bfloat16(v.w);
            __nv_bfloat16* ph = tPh + pr * FS_TSTRIDE + pc;
            __nv_bfloat16* pl = tPl + pr * FS_TSTRIDE + pc;
            *reinterpret_cast<__nv_bfloat162*>(ph)     = __nv_bfloat162(h0, h1);
            *reinterpret_cast<__nv_bfloat162*>(ph + 2) = __nv_bfloat162(h2, h3);
            *reinterpret_cast<__nv_bfloat162*>(pl)     = __nv_bfloat162(
                __float2bfloat16(v.x - __bfloat162float(h0)),
                __float2bfloat16(v.y - __bfloat162float(h1)));
            *reinterpret_cast<__nv_bfloat162*>(pl + 2) = __nv_bfloat162(
                __float2bfloat16(v.z - __bfloat162float(h2)),
                __float2bfloat16(v.w - __bfloat162float(h3)));
        }
        __syncthreads();

        const uint32_t uVh = (t & 1) ? uK1h : uK0h;
        const uint32_t uVl = (t & 1) ? uK1l : uK0l;

#pragma unroll
        for (int k0 = 0; k0 < 64; k0 += 16) {
            uint32_t aoff = (uint32_t)((wm * 16 + lrow) * FS_TSTRIDE + k0 + lcol) * 2;
            uint32_t ah[4], al[4];
            LDSM_X4(ah[0], ah[1], ah[2], ah[3], uQh + aoff);
            LDSM_X4(al[0], al[1], al[2], al[3], uQl + aoff);
            uint32_t boff = (uint32_t)((k0 + (lane & 15)) * FS_TSTRIDE + wn * 8) * 2;
            uint32_t bhf[2], blf[2];
            LDSM_X2_T(bhf[0], bhf[1], uVh + boff);
            LDSM_X2_T(blf[0], blf[1], uVl + boff);
            MMA16816(c2, ah, bhf);
            MMA16816(c2, ah, blf);
            MMA16816(c2, al, bhf);
        }
        __syncthreads();

        if (t + 2 < ntiles) {
            const int tn = (t + 2) * 64;
            const uint32_t dVh = (t & 1) ? uK1h : uK0h;
            const uint32_t dVl = (t & 1) ? uK1l : uK0l;
            const char* gVh = (const char*)(g_Vh + ((size_t)(b * SEQ + tn + klr)) * DMODEL + h * DK);
            const char* gVl = (const char*)(g_Vl + ((size_t)(b * SEQ + tn + klr)) * DMODEL + h * DK);
            cp_async16(dVh + klr * 144 + kcb, gVh + kcb);
            cp_async16(dVl + klr * 144 + kcb, gVl + kcb);
            cp_commit();
        }
    }

    // ctx epilogue (bf16 hi/lo)
    {
        const int r0 = wm * 16 + (lane >> 2);
        const int col = wn * 8 + (lane & 3) * 2;
#pragma unroll
        for (int half = 0; half < 2; half++) {
            const int s = s0 + r0 + half * 8;
            const float v0 = c2[half * 2], v1 = c2[half * 2 + 1];
            __nv_bfloat16 h0 = __float2bfloat16(v0);
            __nv_bfloat16 h1 = __float2bfloat16(v1);
            size_t o = ((size_t)(b * SEQ + s)) * DMODEL + h * DK + col;
            *reinterpret_cast<__nv_bfloat162*>(g_Ch + o) = __nv_bfloat162(h0, h1);
            *reinterpret_cast<__nv_bfloat162*>(g_Cl + o) = __nv_bfloat162(
                __float2bfloat16(v0 - __bfloat162float(h0)),
                __float2bfloat16(v1 - __bfloat162float(h1)));
        }
    }
}

// ===========================================================================
// attn head-mean (fp16 P; half2 vectorized)
// ===========================================================================
__global__ void __launch_bounds__(256)
mean_kernel(float* __restrict__ out2)
{
    const size_t pidx = (size_t)blockIdx.x * 256 + threadIdx.x;
    const int b = (int)(pidx >> 17);
    const int r = (int)(pidx & 131071);
    const int s  = r >> 8;
    const int t2 = (r & 255) * 2;
    float2* o = reinterpret_cast<float2*>(out2) + pidx;
    if (t2 > s) { *o = make_float2(0.f, 0.f); return; }
    float s0 = 0.f, s1 = 0.f;
#pragma unroll
    for (int h = 0; h < NHEAD; h++) {
        const __half2 p = *reinterpret_cast<const __half2*>(
            g_Pm + ((size_t)(b * NHEAD + h) * SEQ + s) * SEQ + t2);
        float2 f = __half22float2(p);
        s0 += f.x; s1 += f.y;
    }
    *o = make_float2(s0 * (1.f / NHEAD), (t2 + 1 <= s) ? s1 * (1.f / NHEAD) : 0.f);
}

// ===========================================================================
// Launch
// ===========================================================================
extern "C" void kernel_launch(void* const* d_in, const int* in_sizes, int n_in,
                              void* d_out, int out_size)
{
    const float* query = (const float*)d_in[0];
    const float* key   = (const float*)d_in[1];
    const float* value = (const float*)d_in[2];
    const float* wq_w  = (const float*)d_in[3];
    const float* wq_b  = (const float*)d_in[4];
    const float* wk_w  = (const float*)d_in[5];
    const float* wk_b  = (const float*)d_in[6];
    const float* wv_w  = (const float*)d_in[7];
    const float* wv_b  = (const float*)d_in[8];
    const float* wo_w  = (const float*)d_in[9];
    const float* wo_b  = (const float*)d_in[10];
    const float* rel_bias = (const float*)d_in[11];

    float* out  = (float*)d_out;
    const size_t out1_elems = (size_t)MTOT * DMODEL;
    const size_t out2_elems = (size_t)BATCH * SEQ * SEQ;
    float* out2 = out + out1_elems;

    __nv_bfloat16 *ahi, *alo, *whi, *wlo, *qh, *ql, *kh, *kl, *vh, *vl, *ch, *cl;
    cudaGetSymbolAddress((void**)&ahi, g_Ahi);
    cudaGetSymbolAddress((void**)&alo, g_Alo);
    cudaGetSymbolAddress((void**)&whi, g_Whi);
    cudaGetSymbolAddress((void**)&wlo, g_Wlo);
    cudaGetSymbolAddress((void**)&qh, g_Qh);
    cudaGetSymbolAddress((void**)&ql, g_Ql);
    cudaGetSymbolAddress((void**)&kh, g_Kh);
    cudaGetSymbolAddress((void**)&kl, g_Kl);
    cudaGetSymbolAddress((void**)&vh, g_Vh);
    cudaGetSymbolAddress((void**)&vl, g_Vl);
    cudaGetSymbolAddress((void**)&ch, g_Ch);
    cudaGetSymbolAddress((void**)&cl, g_Cl);

    cudaFuncSetAttribute(fused_attention,
                         cudaFuncAttributeMaxDynamicSharedMemorySize, FA_SMEM);
    cudaFuncSetAttribute(gemm_qkv,
                         cudaFuncAttributeMaxDynamicSharedMemorySize, GEMM_SMEM);
    cudaFuncSetAttribute(gemm_out,
                         cudaFuncAttributeMaxDynamicSharedMemorySize, GEMM_SMEM);

    const int nA4 = MTOT * DMODEL / 4;
    const int nW4 = DMODEL * DMODEL / 4;
    const size_t wstride = (size_t)DMODEL * DMODEL;

    split3_bf16<<<dim3(nA4 / 256, 3), 256>>>(query, key, value, ahi, alo, nA4);
    split4_bf16<<<dim3(nW4 / 256, 4), 256>>>(wq_w, wk_w, wv_w, wo_w, whi, wlo, nW4);

    gemm_qkv<<<dim3(DMODEL / 128, MTOT / 128, 3), 256, GEMM_SMEM>>>(
        ahi, alo, whi, wlo, wq_b, wk_b, wv_b, qh, ql, kh, kl, vh, vl);

    fused_attention<<<dim3(SEQ / FA_SROWS, BH), 512, FA_SMEM>>>(rel_bias);

    if ((size_t)out_size >= out1_elems + out2_elems) {
        mean_kernel<<<(unsigned)(out2_elems / 512), 256>>>(out2);
    }

    gemm_out<<<dim3(DMODEL / 128, MTOT / 128), 256, GEMM_SMEM>>>(
        ch, cl, whi + 3 * wstride, wlo + 3 * wstride, wo_b, out);
}

// round 17
// speedup vs baseline: 1.0937x; 1.0099x over previous
#include <cuda_runtime.h>
#include <cuda_bf16.h>
#include <cuda_fp16.h>
#include <cstdint>
#include <math.h>

#define BATCH 16
#define SEQ   512
#define DMODEL 1024
#define NHEAD 16
#define DK    64
#define BH    (BATCH * NHEAD)
#define MTOT (BATCH * SEQ)

// ===========================================================================
// Portable PTX helpers
// ===========================================================================
__device__ __forceinline__ uint32_t smem_to_u32(const void* p) {
    uint32_t a;
    asm("{ .reg .u64 t; cvta.to.shared.u64 t, %1; cvt.u32.u64 %0, t; }" : "=r"(a) : "l"(p));
    return a;
}
__device__ __forceinline__ void cp_async16(uint32_t smem_addr, const void* gptr) {
    asm volatile("cp.async.cg.shared.global [%0], [%1], 16;" :: "r"(smem_addr), "l"(gptr) : "memory");
}
__device__ __forceinline__ void cp_commit() { asm volatile("cp.async.commit_group;" ::: "memory"); }
__device__ __forceinline__ void cp_wait1()  { asm volatile("cp.async.wait_group 1;" ::: "memory"); }
__device__ __forceinline__ void cp_wait0()  { asm volatile("cp.async.wait_group 0;" ::: "memory"); }

#define LDSM_X4(r0, r1, r2, r3, addr) \
    asm volatile("ldmatrix.sync.aligned.m8n8.x4.shared.b16 {%0,%1,%2,%3}, [%4];" \
        : "=r"(r0), "=r"(r1), "=r"(r2), "=r"(r3) : "r"(addr))

#define LDSM_X4_T(r0, r1, r2, r3, addr) \
    asm volatile("ldmatrix.sync.aligned.m8n8.x4.trans.shared.b16 {%0,%1,%2,%3}, [%4];" \
        : "=r"(r0), "=r"(r1), "=r"(r2), "=r"(r3) : "r"(addr))

#define MMA16816(c, a, b) \
    asm volatile("mma.sync.aligned.m16n8k16.row.col.f32.bf16.bf16.f32 " \
        "{%0,%1,%2,%3}, {%4,%5,%6,%7}, {%8,%9}, {%0,%1,%2,%3};" \
        : "+f"((c)[0]), "+f"((c)[1]), "+f"((c)[2]), "+f"((c)[3]) \
        : "r"((a)[0]), "r"((a)[1]), "r"((a)[2]), "r"((a)[3]), "r"((b)[0]), "r"((b)[1]))

// ===========================================================================
// Scratch
// ===========================================================================
__device__ __nv_bfloat16 g_Ahi[(size_t)3 * MTOT * DMODEL];
__device__ __nv_bfloat16 g_Alo[(size_t)3 * MTOT * DMODEL];
__device__ __nv_bfloat16 g_Whi[(size_t)4 * DMODEL * DMODEL];
__device__ __nv_bfloat16 g_Wlo[(size_t)4 * DMODEL * DMODEL];
__device__ __nv_bfloat16 g_Qh[(size_t)MTOT * DMODEL];
__device__ __nv_bfloat16 g_Ql[(size_t)MTOT * DMODEL];
__device__ __nv_bfloat16 g_Kh[(size_t)MTOT * DMODEL];
__device__ __nv_bfloat16 g_Kl[(size_t)MTOT * DMODEL];
__device__ __nv_bfloat16 g_Vh[(size_t)MTOT * DMODEL];
__device__ __nv_bfloat16 g_Vl[(size_t)MTOT * DMODEL];
__device__ __nv_bfloat16 g_Ch[(size_t)MTOT * DMODEL];
__device__ __nv_bfloat16 g_Cl[(size_t)MTOT * DMODEL];
__device__ __half g_Pm[(size_t)BH * SEQ * SEQ];

// ===========================================================================
// fp32 -> bf16 hi/lo splits
// ===========================================================================
__device__ __forceinline__ void split_store(const float4 v, __nv_bfloat16* hi,
                                            __nv_bfloat16* lo, size_t i4)
{
    __nv_bfloat16 h0 = __float2bfloat16(v.x);
    __nv_bfloat16 h1 = __float2bfloat16(v.y);
    __nv_bfloat16 h2 = __float2bfloat16(v.z);
    __nv_bfloat16 h3 = __float2bfloat16(v.w);
    __nv_bfloat162* hp = reinterpret_cast<__nv_bfloat162*>(hi);
    __nv_bfloat162* lp = reinterpret_cast<__nv_bfloat162*>(lo);
    hp[2 * i4]     = __nv_bfloat162(h0, h1);
    hp[2 * i4 + 1] = __nv_bfloat162(h2, h3);
    lp[2 * i4]     = __nv_bfloat162(__float2bfloat16(v.x - __bfloat162float(h0)),
                                    __float2bfloat16(v.y - __bfloat162float(h1)));
    lp[2 * i4 + 1] = __nv_bfloat162(__float2bfloat16(v.z - __bfloat162float(h2)),
                                    __float2bfloat16(v.w - __bfloat162float(h3)));
}

__global__ void __launch_bounds__(256)
split3_bf16(const float* __restrict__ q, const float* __restrict__ k,
            const float* __restrict__ v, __nv_bfloat16* __restrict__ hi,
            __nv_bfloat16* __restrict__ lo, int n4)
{
    int i = blockIdx.x * 256 + threadIdx.x;
    if (i >= n4) return;
    const int z = blockIdx.y;
    const float* src = (z == 0) ? q : ((z == 1) ? k : v);
    split_store(reinterpret_cast<const float4*>(src)[i], hi, lo, (size_t)z * n4 + i);
}

__global__ void __launch_bounds__(256)
split4_bf16(const float* __restrict__ w0, const float* __restrict__ w1,
            const float* __restrict__ w2, const float* __restrict__ w3,
            __nv_bfloat16* __restrict__ hi, __nv_bfloat16* __restrict__ lo, int n4)
{
    int i = blockIdx.x * 256 + threadIdx.x;
    if (i >= n4) return;
    const int z = blockIdx.y;
    const float* src = (z == 0) ? w0 : ((z == 1) ? w1 : ((z == 2) ? w2 : w3));
    split_store(reinterpret_cast<const float4*>(src)[i], hi, lo, (size_t)z * n4 + i);
}

// ===========================================================================
// HMMA GEMM core (bf16x3), 128x128 tile, BK=32, 2-stage, 2 CTAs/SM.
// ===========================================================================
#define GK 1024
#define NK32 (GK / 32)
#define T_STRIDE 40
#define TILE_B (128 * T_STRIDE * 2)
#define STAGE_B (4 * TILE_B)
#define GEMM_SMEM (2 * STAGE_B)

__device__ __forceinline__ void
gemm_core(const __nv_bfloat16* __restrict__ Ahi, const __nv_bfloat16* __restrict__ Alo,
          const __nv_bfloat16* __restrict__ Bhi, const __nv_bfloat16* __restrict__ Blo,
          const float* __restrict__ bias, float* __restrict__ C,
          __nv_bfloat16* __restrict__ Chi, __nv_bfloat16* __restrict__ Clo,
          char* smem, int mBase, int nBase)
{
    const int tid  = threadIdx.x;
    const int lane = tid & 31;
    const int wid  = tid >> 5;
    const int wm   = wid & 3;
    const int wn   = wid >> 2;
    const uint32_t su32 = smem_to_u32(smem);

    float c[2][8][4];
#pragma unroll
    for (int mf = 0; mf < 2; mf++)
#pragma unroll
        for (int nf = 0; nf < 8; nf++)
#pragma unroll
            for (int j = 0; j < 4; j++) c[mf][nf][j] = 0.f;

    const int lr = tid >> 1;
    const int lk = (tid & 1) * 16;
    const __nv_bfloat16* gp0 = Ahi + (size_t)(mBase + lr) * GK + lk;
    const __nv_bfloat16* gp1 = Alo + (size_t)(mBase + lr) * GK + lk;
    const __nv_bfloat16* gp2 = Bhi + (size_t)(nBase + lr) * GK + lk;
    const __nv_bfloat16* gp3 = Blo + (size_t)(nBase + lr) * GK + lk;
    const uint32_t soff = (uint32_t)(lr * T_STRIDE + lk) * 2;

    auto load_chunk = [&](int st, int kc) {
        uint32_t base = su32 + (uint32_t)st * STAGE_B + soff;
        const int ko = kc * 32;
        cp_async16(base,               gp0 + ko);
        cp_async16(base + 16,          gp0 + ko + 8);
        cp_async16(base + TILE_B,      gp1 + ko);
        cp_async16(base + TILE_B + 16, gp1 + ko + 8);
        cp_async16(base + 2 * TILE_B,      gp2 + ko);
        cp_async16(base + 2 * TILE_B + 16, gp2 + ko + 8);
        cp_async16(base + 3 * TILE_B,      gp3 + ko);
        cp_async16(base + 3 * TILE_B + 16, gp3 + ko + 8);
    };

    load_chunk(0, 0); cp_commit();
    load_chunk(1, 1); cp_commit();

    const int lrow = lane & 15;
    const int lcol = (lane >> 4) * 8;

    for (int i = 0; i < NK32; i++) {
        if (i + 1 < NK32) cp_wait1(); else cp_wait0();
        __syncthreads();

        const uint32_t sb = su32 + (uint32_t)(i & 1) * STAGE_B;
#pragma unroll
        for (int kh = 0; kh < 32; kh += 16) {
            uint32_t bh[8][2], bl[8][2];
#pragma unroll
            for (int g = 0; g < 4; g++) {
                uint32_t addr = sb + 2 * TILE_B +
                    (uint32_t)((wn * 64 + g * 16 + lrow) * T_STRIDE + kh + lcol) * 2;
                LDSM_X4(bh[g * 2][0], bh[g * 2 + 1][0],
                        bh[g * 2][1], bh[g * 2 + 1][1], addr);
                LDSM_X4(bl[g * 2][0], bl[g * 2 + 1][0],
                        bl[g * 2][1], bl[g * 2 + 1][1], addr + TILE_B);
            }
#pragma unroll
            for (int mf = 0; mf < 2; mf++) {
                uint32_t aaddr = sb +
                    (uint32_t)((wm * 32 + mf * 16 + lrow) * T_STRIDE + kh + lcol) * 2;
                uint32_t ah[4], al[4];
                LDSM_X4(ah[0], ah[1], ah[2], ah[3], aaddr);
                LDSM_X4(al[0], al[1], al[2], al[3], aaddr + TILE_B);
#pragma unroll
                for (int nf = 0; nf < 8; nf++) {
                    MMA16816(c[mf][nf], ah, bh[nf]);
                    MMA16816(c[mf][nf], ah, bl[nf]);
                    MMA16816(c[mf][nf], al, bh[nf]);
                }
            }
        }
        __syncthreads();

        if (i + 2 < NK32) {
            load_chunk(i & 1, i + 2);
            cp_commit();
        }
    }

#pragma unroll
    for (int mf = 0; mf < 2; mf++) {
        const int row0 = mBase + wm * 32 + mf * 16 + (lane >> 2);
#pragma unroll
        for (int nf = 0; nf < 8; nf++) {
            const int col = nBase + wn * 64 + nf * 8 + (lane & 3) * 2;
            const float b0 = bias[col], b1 = bias[col + 1];
            float v00 = c[mf][nf][0] + b0, v01 = c[mf][nf][1] + b1;
            float v10 = c[mf][nf][2] + b0, v11 = c[mf][nf][3] + b1;
            if (Chi) {
                __nv_bfloat16 h00 = __float2bfloat16(v00), h01 = __float2bfloat16(v01);
                __nv_bfloat16 h10 = __float2bfloat16(v10), h11 = __float2bfloat16(v11);
                size_t o0 = (size_t)row0 * DMODEL + col, o1 = (size_t)(row0 + 8) * DMODEL + col;
                *reinterpret_cast<__nv_bfloat162*>(Chi + o0) = __nv_bfloat162(h00, h01);
                *reinterpret_cast<__nv_bfloat162*>(Chi + o1) = __nv_bfloat162(h10, h11);
                *reinterpret_cast<__nv_bfloat162*>(Clo + o0) = __nv_bfloat162(
                    __float2bfloat16(v00 - __bfloat162float(h00)),
                    __float2bfloat16(v01 - __bfloat162float(h01)));
                *reinterpret_cast<__nv_bfloat162*>(Clo + o1) = __nv_bfloat162(
                    __float2bfloat16(v10 - __bfloat162float(h10)),
                    __float2bfloat16(v11 - __bfloat162float(h11)));
            } else {
                *reinterpret_cast<float2*>(C + (size_t)row0 * DMODEL + col)       = make_float2(v00, v01);
                *reinterpret_cast<float2*>(C + (size_t)(row0 + 8) * DMODEL + col) = make_float2(v10, v11);
            }
        }
    }
}

__global__ void __launch_bounds__(256, 2)
gemm_qkv(const __nv_bfloat16* __restrict__ Ahi, const __nv_bfloat16* __restrict__ Alo,
         const __nv_bfloat16* __restrict__ Whi, const __nv_bfloat16* __restrict__ Wlo,
         const float* __restrict__ b0, const float* __restrict__ b1, const float* __restrict__ b2,
         __nv_bfloat16* __restrict__ o0h, __nv_bfloat16* __restrict__ o0l,
         __nv_bfloat16* __restrict__ o1h, __nv_bfloat16* __restrict__ o1l,
         __nv_bfloat16* __restrict__ o2h, __nv_bfloat16* __restrict__ o2l)
{
    extern __shared__ __align__(128) char smem[];
    const int z = blockIdx.z;
    const size_t aoff = (size_t)z * MTOT * GK;
    const size_t woff = (size_t)z * DMODEL * GK;
    const float* bias = (z == 0) ? b0 : ((z == 1) ? b1 : b2);
    __nv_bfloat16* oh = (z == 0) ? o0h : ((z == 1) ? o1h : o2h);
    __nv_bfloat16* ol = (z == 0) ? o0l : ((z == 1) ? o1l : o2l);
    gemm_core(Ahi + aoff, Alo + aoff, Whi + woff, Wlo + woff,
              bias, nullptr, oh, ol, smem, blockIdx.y * 128, blockIdx.x * 128);
}

__global__ void __launch_bounds__(256, 2)
gemm_out(const __nv_bfloat16* __restrict__ Ahi, const __nv_bfloat16* __restrict__ Alo,
         const __nv_bfloat16* __restrict__ Whi, const __nv_bfloat16* __restrict__ Wlo,
         const float* __restrict__ bias, float* __restrict__ C)
{
    extern __shared__ __align__(128) char smem[];
    gemm_core(Ahi, Alo, Whi, Wlo, bias, C, nullptr, nullptr,
              smem, blockIdx.y * 128, blockIdx.x * 128);
}

// ===========================================================================
// Fully fused attention: 32 s-rows per CTA, 512 threads (16 warps, 2x8 grid),
// 2 CTAs/SM. x4 ldmatrix for K/V; causal warp/k-block skipping.
// ===========================================================================
#define S_STRIDE 516
#define FA_SROWS 32
#define FA_SBYTES (FA_SROWS * S_STRIDE * 4)
#define FS_TSTRIDE 72
#define QTILE (FA_SROWS * FS_TSTRIDE)
#define QTILEB (QTILE * 2)
#define KTILE (64 * FS_TSTRIDE)
#define KTILEB (KTILE * 2)
#define FA_SMEM (FA_SBYTES + 2 * QTILEB + 4 * KTILEB)

__global__ void __launch_bounds__(512, 2)
fused_attention(const float* __restrict__ rel_bias)
{
    extern __shared__ __align__(128) char fsmem[];
    float* S = reinterpret_cast<float*>(fsmem);
    const uint32_t sbase = smem_to_u32(fsmem);
    const uint32_t uQh  = sbase + FA_SBYTES;
    const uint32_t uQl  = uQh + QTILEB;
    const uint32_t uK0h = uQl + QTILEB;
    const uint32_t uK0l = uK0h + KTILEB;
    const uint32_t uK1h = uK0l + KTILEB;
    const uint32_t uK1l = uK1h + KTILEB;

    const int s0 = (gridDim.x - 1 - blockIdx.x) * FA_SROWS;
    const int bh = blockIdx.y;
    const int b  = bh >> 4;
    const int h  = bh & 15;
    const int tid = threadIdx.x, lane = tid & 31, wid = tid >> 5;
    const int wm = wid & 1;
    const int wn = wid >> 1;

    const int ntiles = s0 / 64 + 1;
    const int lrow = lane & 15;
    const int lcol = (lane >> 4) * 8;

    const int klr = tid >> 3;
    const int kcb = (tid & 7) * 16;
    const int qlr = tid >> 3;
    const int qcb = (tid & 7) * 16;

    // ---------------- Phase 1: scores -> S ----------------
    {
        if (tid < 256) {
            const char* gQh = (const char*)(g_Qh + ((size_t)(b * SEQ + s0 + qlr)) * DMODEL + h * DK);
            const char* gQl = (const char*)(g_Ql + ((size_t)(b * SEQ + s0 + qlr)) * DMODEL + h * DK);
            cp_async16(uQh + qlr * 144 + qcb, gQh + qcb);
            cp_async16(uQl + qlr * 144 + qcb, gQl + qcb);
        }
        const char* gKh = (const char*)(g_Kh + ((size_t)(b * SEQ + klr)) * DMODEL + h * DK);
        const char* gKl = (const char*)(g_Kl + ((size_t)(b * SEQ + klr)) * DMODEL + h * DK);
        cp_async16(uK0h + klr * 144 + kcb, gKh + kcb);
        cp_async16(uK0l + klr * 144 + kcb, gKl + kcb);
        cp_commit();
    }
    if (ntiles > 1) {
        const char* gKh = (const char*)(g_Kh + ((size_t)(b * SEQ + 64 + klr)) * DMODEL + h * DK);
        const char* gKl = (const char*)(g_Kl + ((size_t)(b * SEQ + 64 + klr)) * DMODEL + h * DK);
        cp_async16(uK1h + klr * 144 + kcb, gKh + kcb);
        cp_async16(uK1l + klr * 144 + kcb, gKl + kcb);
        cp_commit();
    }

    for (int t = 0; t < ntiles; t++) {
        const int t0 = t * 64;
        if (t + 1 < ntiles) cp_wait1(); else cp_wait0();
        __syncthreads();

        const uint32_t uKh = (t & 1) ? uK1h : uK0h;
        const uint32_t uKl = (t & 1) ? uK1l : uK0l;

        // warp fully above diagonal? (cols all > max row s0+31)
        const bool wskip = (t0 + wn * 8 > s0 + 31);

        if (!wskip) {
            float c[4];
#pragma unroll
            for (int j = 0; j < 4; j++) c[j] = 0.f;

#pragma unroll
            for (int k0 = 0; k0 < 64; k0 += 32) {
                // K frags for k0 and k0+16 in one x4 (hi, lo)
                uint32_t boff = (uint32_t)((wn * 8 + (lane & 7)) * FS_TSTRIDE +
                                           k0 + ((lane >> 3) & 3) * 8) * 2;
                uint32_t bh4[4], bl4[4];
                LDSM_X4(bh4[0], bh4[1], bh4[2], bh4[3], uKh + boff);
                LDSM_X4(bl4[0], bl4[1], bl4[2], bl4[3], uKl + boff);
#pragma unroll
                for (int kk = 0; kk < 2; kk++) {
                    uint32_t aoff = (uint32_t)((wm * 16 + lrow) * FS_TSTRIDE +
                                               k0 + kk * 16 + lcol) * 2;
                    uint32_t ah[4], al[4];
                    LDSM_X4(ah[0], ah[1], ah[2], ah[3], uQh + aoff);
                    LDSM_X4(al[0], al[1], al[2], al[3], uQl + aoff);
                    uint32_t* bh = bh4 + kk * 2;
                    uint32_t* bl = bl4 + kk * 2;
                    MMA16816(c, ah, bh);
                    MMA16816(c, ah, bl);
                    MMA16816(c, al, bh);
                }
            }

            {
                const int r0 = wm * 16 + (lane >> 2);
                const int sg0 = s0 + r0, sg1 = sg0 + 8;
                const int col = wn * 8 + (lane & 3) * 2;
                const int tg = t0 + col;
                float2 rb0 = *reinterpret_cast<const float2*>(
                    rel_bias + ((size_t)h * SEQ + sg0) * SEQ + tg);
                float2 rb1 = *reinterpret_cast<const float2*>(
                    rel_bias + ((size_t)h * SEQ + sg1) * SEQ + tg);
                float v00 = c[0] * 0.125f + rb0.x; if (tg     > sg0) v00 = -INFINITY;
                float v01 = c[1] * 0.125f + rb0.y; if (tg + 1 > sg0) v01 = -INFINITY;
                float v10 = c[2] * 0.125f + rb1.x; if (tg     > sg1) v10 = -INFINITY;
                float v11 = c[3] * 0.125f + rb1.y; if (tg + 1 > sg1) v11 = -INFINITY;
                *reinterpret_cast<float2*>(&S[r0 * S_STRIDE + tg])       = make_float2(v00, v01);
                *reinterpret_cast<float2*>(&S[(r0 + 8) * S_STRIDE + tg]) = make_float2(v10, v11);
            }
        }
        __syncthreads();

        if (t + 2 < ntiles) {
            const int tn = (t + 2) * 64;
            const uint32_t dKh = (t & 1) ? uK1h : uK0h;
            const uint32_t dKl = (t & 1) ? uK1l : uK0l;
            const char* gKh = (const char*)(g_Kh + ((size_t)(b * SEQ + tn + klr)) * DMODEL + h * DK);
            const char* gKl = (const char*)(g_Kl + ((size_t)(b * SEQ + tn + klr)) * DMODEL + h * DK);
            cp_async16(dKh + klr * 144 + kcb, gKh + kcb);
            cp_async16(dKl + klr * 144 + kcb, gKl + kcb);
            cp_commit();
        }
    }

    // ---------------- Phase 2: softmax (2 rows per warp) ----------------
    const int Lt = ntiles * 64;
    for (int r = wid * 2; r < wid * 2 + 2; r++) {
        const int s = s0 + r;
        const int L = s + 1;
        float* row = S + r * S_STRIDE;

        float m = -INFINITY;
        for (int ci = lane; ci < L; ci += 32) m = fmaxf(m, row[ci]);
#pragma unroll
        for (int o = 16; o; o >>= 1) m = fmaxf(m, __shfl_xor_sync(0xffffffffu, m, o));

        float sum = 0.f;
        for (int ci = lane; ci < L; ci += 32) {
            float e = __expf(row[ci] - m);
            row[ci] = e;
            sum += e;
        }
#pragma unroll
        for (int o = 16; o; o >>= 1) sum += __shfl_xor_sync(0xffffffffu, sum, o);
        const float inv = 1.f / sum;

        __half* om = g_Pm + ((size_t)bh * SEQ + s) * SEQ;
        for (int ci = lane; ci < Lt; ci += 32) {
            float p = (ci < L) ? row[ci] * inv : 0.f;
            row[ci] = p;
            om[ci] = __float2half_rn(p);
        }
    }
    __syncthreads();

    // ---------------- Phase 3: ctx = P @ V ----------------
    float c2[4];
#pragma unroll
    for (int j = 0; j < 4; j++) c2[j] = 0.f;

    {
        const char* gVh = (const char*)(g_Vh + ((size_t)(b * SEQ + klr)) * DMODEL + h * DK);
        const char* gVl = (const char*)(g_Vl + ((size_t)(b * SEQ + klr)) * DMODEL + h * DK);
        cp_async16(uK0h + klr * 144 + kcb, gVh + kcb);
        cp_async16(uK0l + klr * 144 + kcb, gVl + kcb);
        cp_commit();
    }
    if (ntiles > 1) {
        const char* gVh = (const char*)(g_Vh + ((size_t)(b * SEQ + 64 + klr)) * DMODEL + h * DK);
        const char* gVl = (const char*)(g_Vl + ((size_t)(b * SEQ + 64 + klr)) * DMODEL + h * DK);
        cp_async16(uK1h + klr * 144 + kcb, gVh + kcb);
        cp_async16(uK1l + klr * 144 + kcb, gVl + kcb);
        cp_commit();
    }

    __nv_bfloat16* tPh = reinterpret_cast<__nv_bfloat16*>(fsmem + FA_SBYTES);
    __nv_bfloat16* tPl = tPh + QTILE;

    for (int t = 0; t < ntiles; t++) {
        const int t0 = t * 64;
        if (t + 1 < ntiles) cp_wait1(); else cp_wait0();

        {
            const int pr = tid >> 4;
            const int pc = (tid & 15) * 4;
            const float* srow = S + pr * S_STRIDE + t0 + pc;
            float4 v = *reinterpret_cast<const float4*>(srow);
            __nv_bfloat16 h0 = __float2bfloat16(v.x);
            __nv_bfloat16 h1 = __float2bfloat16(v.y);
            __nv_bfloat16 h2 = __float2bfloat16(v.z);
            __nv_bfloat16 h3 = __float2bfloat16(v.w);
            __nv_bfloat16* ph = tPh + pr * FS_TSTRIDE + pc;
            __nv_bfloat16* pl = tPl + pr * FS_TSTRIDE + pc;
            *reinterpret_cast<__nv_bfloat162*>(ph)     = __nv_bfloat162(h0, h1);
            *reinterpret_cast<__nv_bfloat162*>(ph + 2) = __nv_bfloat162(h2, h3);
            *reinterpret_cast<__nv_bfloat162*>(pl)     = __nv_bfloat162(
                __float2bfloat16(v.x - __bfloat162float(h0)),
                __float2bfloat16(v.y - __bfloat162float(h1)));
            *reinterpret_cast<__nv_bfloat162*>(pl + 2) = __nv_bfloat162(
                __float2bfloat16(v.z - __bfloat162float(h2)),
                __float2bfloat16(v.w - __bfloat162float(h3)));
        }
        __syncthreads();

        const uint32_t uVh = (t & 1) ? uK1h : uK0h;
        const uint32_t uVl = (t & 1) ? uK1l : uK0l;

#pragma unroll
        for (int k0 = 0; k0 < 64; k0 += 32) {
            // k-block entirely above diagonal for all rows -> P is all zero
            if (t0 + k0 > s0 + 31) break;
            // V frags for k0 and k0+16 in one x4 trans (hi, lo)
            uint32_t boff = (uint32_t)((k0 + lane) * FS_TSTRIDE + wn * 8) * 2;
            uint32_t bh4[4], bl4[4];
            LDSM_X4_T(bh4[0], bh4[1], bh4[2], bh4[3], uVh + boff);
            LDSM_X4_T(bl4[0], bl4[1], bl4[2], bl4[3], uVl + boff);
#pragma unroll
            for (int kk = 0; kk < 2; kk++) {
                uint32_t aoff = (uint32_t)((wm * 16 + lrow) * FS_TSTRIDE +
                                           k0 + kk * 16 + lcol) * 2;
                uint32_t ah[4], al[4];
                LDSM_X4(ah[0], ah[1], ah[2], ah[3], uQh + aoff);
                LDSM_X4(al[0], al[1], al[2], al[3], uQl + aoff);
                uint32_t* bh = bh4 + kk * 2;
                uint32_t* bl = bl4 + kk * 2;
                MMA16816(c2, ah, bh);
                MMA16816(c2, ah, bl);
                MMA16816(c2, al, bh);
            }
        }
        __syncthreads();

        if (t + 2 < ntiles) {
            const int tn = (t + 2) * 64;
            const uint32_t dVh = (t & 1) ? uK1h : uK0h;
            const uint32_t dVl = (t & 1) ? uK1l : uK0l;
            const char* gVh = (const char*)(g_Vh + ((size_t)(b * SEQ + tn + klr)) * DMODEL + h * DK);
            const char* gVl = (const char*)(g_Vl + ((size_t)(b * SEQ + tn + klr)) * DMODEL + h * DK);
            cp_async16(dVh + klr * 144 + kcb, gVh + kcb);
            cp_async16(dVl + klr * 144 + kcb, gVl + kcb);
            cp_commit();
        }
    }

    // ctx epilogue (bf16 hi/lo)
    {
        const int r0 = wm * 16 + (lane >> 2);
        const int col = wn * 8 + (lane & 3) * 2;
#pragma unroll
        for (int half = 0; half < 2; half++) {
            const int s = s0 + r0 + half * 8;
            const float v0 = c2[half * 2], v1 = c2[half * 2 + 1];
            __nv_bfloat16 h0 = __float2bfloat16(v0);
            __nv_bfloat16 h1 = __float2bfloat16(v1);
            size_t o = ((size_t)(b * SEQ + s)) * DMODEL + h * DK + col;
            *reinterpret_cast<__nv_bfloat162*>(g_Ch + o) = __nv_bfloat162(h0, h1);
            *reinterpret_cast<__nv_bfloat162*>(g_Cl + o) = __nv_bfloat162(
                __float2bfloat16(v0 - __bfloat162float(h0)),
                __float2bfloat16(v1 - __bfloat162float(h1)));
        }
    }
}

// ===========================================================================
// attn head-mean (fp16 P; half2 vectorized)
// ===========================================================================
__global__ void __launch_bounds__(256)
mean_kernel(float* __restrict__ out2)
{
    const size_t pidx = (size_t)blockIdx.x * 256 + threadIdx.x;
    const int b = (int)(pidx >> 17);
    const int r = (int)(pidx & 131071);
    const int s  = r >> 8;
    const int t2 = (r & 255) * 2;
    float2* o = reinterpret_cast<float2*>(out2) + pidx;
    if (t2 > s) { *o = make_float2(0.f, 0.f); return; }
    float s0 = 0.f, s1 = 0.f;
#pragma unroll
    for (int h = 0; h < NHEAD; h++) {
        const __half2 p = *reinterpret_cast<const __half2*>(
            g_Pm + ((size_t)(b * NHEAD + h) * SEQ + s) * SEQ + t2);
        float2 f = __half22float2(p);
        s0 += f.x; s1 += f.y;
    }
    *o = make_float2(s0 * (1.f / NHEAD), (t2 + 1 <= s) ? s1 * (1.f / NHEAD) : 0.f);
}

// ===========================================================================
// Launch
// ===========================================================================
extern "C" void kernel_launch(void* const* d_in, const int* in_sizes, int n_in,
                              void* d_out, int out_size)
{
    const float* query = (const float*)d_in[0];
    const float* key   = (const float*)d_in[1];
    const float* value = (const float*)d_in[2];
    const float* wq_w  = (const float*)d_in[3];
    const float* wq_b  = (const float*)d_in[4];
    const float* wk_w  = (const float*)d_in[5];
    const float* wk_b  = (const float*)d_in[6];
    const float* wv_w  = (const float*)d_in[7];
    const float* wv_b  = (const float*)d_in[8];
    const float* wo_w  = (const float*)d_in[9];
    const float* wo_b  = (const float*)d_in[10];
    const float* rel_bias = (const float*)d_in[11];

    float* out  = (float*)d_out;
    const size_t out1_elems = (size_t)MTOT * DMODEL;
    const size_t out2_elems = (size_t)BATCH * SEQ * SEQ;
    float* out2 = out + out1_elems;

    __nv_bfloat16 *ahi, *alo, *whi, *wlo, *qh, *ql, *kh, *kl, *vh, *vl, *ch, *cl;
    cudaGetSymbolAddress((void**)&ahi, g_Ahi);
    cudaGetSymbolAddress((void**)&alo, g_Alo);
    cudaGetSymbolAddress((void**)&whi, g_Whi);
    cudaGetSymbolAddress((void**)&wlo, g_Wlo);
    cudaGetSymbolAddress((void**)&qh, g_Qh);
    cudaGetSymbolAddress((void**)&ql, g_Ql);
    cudaGetSymbolAddress((void**)&kh, g_Kh);
    cudaGetSymbolAddress((void**)&kl, g_Kl);
    cudaGetSymbolAddress((void**)&vh, g_Vh);
    cudaGetSymbolAddress((void**)&vl, g_Vl);
    cudaGetSymbolAddress((void**)&ch, g_Ch);
    cudaGetSymbolAddress((void**)&cl, g_Cl);

    cudaFuncSetAttribute(fused_attention,
                         cudaFuncAttributeMaxDynamicSharedMemorySize, FA_SMEM);
    cudaFuncSetAttribute(gemm_qkv,
                         cudaFuncAttributeMaxDynamicSharedMemorySize, GEMM_SMEM);
    cudaFuncSetAttribute(gemm_out,
                         cudaFuncAttributeMaxDynamicSharedMemorySize, GEMM_SMEM);

    const int nA4 = MTOT * DMODEL / 4;
    const int nW4 = DMODEL * DMODEL / 4;
    const size_t wstride = (size_t)DMODEL * DMODEL;

    split3_bf16<<<dim3(nA4 / 256, 3), 256>>>(query, key, value, ahi, alo, nA4);
    split4_bf16<<<dim3(nW4 / 256, 4), 256>>>(wq_w, wk_w, wv_w, wo_w, whi, wlo, nW4);

    gemm_qkv<<<dim3(DMODEL / 128, MTOT / 128, 3), 256, GEMM_SMEM>>>(
        ahi, alo, whi, wlo, wq_b, wk_b, wv_b, qh, ql, kh, kl, vh, vl);

    fused_attention<<<dim3(SEQ / FA_SROWS, BH), 512, FA_SMEM>>>(rel_bias);

    if ((size_t)out_size >= out1_elems + out2_elems) {
        mean_kernel<<<(unsigned)(out2_elems / 512), 256>>>(out2);
    }

    gemm_out<<<dim3(DMODEL / 128, MTOT / 128), 256, GEMM_SMEM>>>(
        ch, cl, whi + 3 * wstride, wlo + 3 * wstride, wo_b, out);
}